// round 14
// baseline (speedup 1.0000x reference)
#include <cuda_runtime.h>
#include <cuda_fp16.h>
#include <cstdint>

constexpr int NB = 8, C = 64, HW = 4096;
constexpr int QT = 128;                // q rows per CTA (32 per warp, 2 mtiles)
constexpr int KT = 64;                 // keys per iteration
constexpr int NKT = HW / KT;           // 64
constexpr float EPS_BN = 1e-5f;
constexpr float QSCALE = 0.125f * 1.4426950408889634f;  // (1/sqrt(64)) * log2(e)
constexpr uint32_t ONE2 = 0x3C003C00u; // half2(1,1)

__device__ __align__(256) float g_scale[C];
__device__ __align__(256) float g_shift[C];
__device__ __align__(256) float g_ps[512];
__device__ __align__(256) float g_pq[512];
__device__ __align__(256) __half g_Q[(size_t)NB * HW * C];   // [n,i,c] pre-scaled
__device__ __align__(256) __half g_Kb[(size_t)NB * HW * C];  // [n,j,c]
__device__ __align__(256) __half g_V[(size_t)NB * HW * C];   // [n,j,c]
__device__ __align__(256) float g_O[(size_t)NB * HW * C];    // [n,i,c]

// ---------- helpers ----------
__device__ __forceinline__ uint32_t smem_u32(const void* p) {
    uint32_t a;
    asm("{ .reg .u64 t; cvta.to.shared.u64 t, %1; cvt.u32.u64 %0, t; }" : "=r"(a) : "l"(p));
    return a;
}
__device__ __forceinline__ void cp_async16(uint32_t s, const void* g) {
    asm volatile("cp.async.cg.shared.global [%0], [%1], 16;" :: "r"(s), "l"(g));
}
__device__ __forceinline__ void cp_commit() { asm volatile("cp.async.commit_group;"); }

// f32 accum, fp16 inputs
__device__ __forceinline__ void mma_f32f16(float* d, const uint32_t* a, uint32_t b0, uint32_t b1) {
    asm volatile(
        "mma.sync.aligned.m16n8k16.row.col.f32.f16.f16.f32 "
        "{%0,%1,%2,%3}, {%4,%5,%6,%7}, {%8,%9}, {%0,%1,%2,%3};"
        : "+f"(d[0]), "+f"(d[1]), "+f"(d[2]), "+f"(d[3])
        : "r"(a[0]), "r"(a[1]), "r"(a[2]), "r"(a[3]), "r"(b0), "r"(b1));
}
// fp16 accum, fp16 inputs (packed D)
__device__ __forceinline__ void mma_f16acc(uint32_t* d, const uint32_t* a, uint32_t b0, uint32_t b1) {
    asm volatile(
        "mma.sync.aligned.m16n8k16.row.col.f16.f16.f16.f16 "
        "{%0,%1}, {%2,%3,%4,%5}, {%6,%7}, {%0,%1};"
        : "+r"(d[0]), "+r"(d[1])
        : "r"(a[0]), "r"(a[1]), "r"(a[2]), "r"(a[3]), "r"(b0), "r"(b1));
}
__device__ __forceinline__ uint32_t h2ex2(uint32_t x) {
    uint32_t y; asm("ex2.approx.f16x2 %0, %1;" : "=r"(y) : "r"(x)); return y;
}
__device__ __forceinline__ void ldsm4(uint32_t* r, uint32_t addr) {
    asm volatile("ldmatrix.sync.aligned.m8n8.x4.shared.b16 {%0,%1,%2,%3}, [%4];"
        : "=r"(r[0]), "=r"(r[1]), "=r"(r[2]), "=r"(r[3]) : "r"(addr));
}
__device__ __forceinline__ void ldsm4t(uint32_t* r, uint32_t addr) {
    asm volatile("ldmatrix.sync.aligned.m8n8.x4.trans.shared.b16 {%0,%1,%2,%3}, [%4];"
        : "=r"(r[0]), "=r"(r[1]), "=r"(r[2]), "=r"(r[3]) : "r"(addr));
}
__device__ __forceinline__ uint32_t packhf(float a, float b) {
    __half2 t = __floats2half2_rn(a, b);
    return *reinterpret_cast<uint32_t*>(&t);
}

// ---------- kernel 1a: BN partial sums ----------
__global__ __launch_bounds__(256) void bn_part(const float* __restrict__ x) {
    int c = blockIdx.x >> 3, s = blockIdx.x & 7, t = threadIdx.x;
    const float* p = x + ((size_t)s * C + c) * HW;
    float sm = 0.f, sq = 0.f;
#pragma unroll
    for (int i = 0; i < HW / 256; i++) { float v = p[t + i * 256]; sm += v; sq += v * v; }
    __shared__ float rs[256], rq[256];
    rs[t] = sm; rq[t] = sq; __syncthreads();
    for (int o = 128; o > 0; o >>= 1) {
        if (t < o) { rs[t] += rs[t + o]; rq[t] += rq[t + o]; }
        __syncthreads();
    }
    if (t == 0) { g_ps[c * 8 + s] = rs[0]; g_pq[c * 8 + s] = rq[0]; }
}

// ---------- kernel 1b: BN finalize ----------
__global__ void bn_fin(const float* __restrict__ gamma, const float* __restrict__ beta) {
    int c = threadIdx.x;
    float sm = 0.f, sq = 0.f;
#pragma unroll
    for (int k = 0; k < 8; k++) { sm += g_ps[c * 8 + k]; sq += g_pq[c * 8 + k]; }
    float inv = 1.0f / (float)(NB * HW);
    float mean = sm * inv;
    float var = sq * inv - mean * mean;
    float sc = rsqrtf(var + EPS_BN) * gamma[c];
    g_scale[c] = sc;
    g_shift[c] = beta[c] - mean * sc;
}

// ---------- kernel 2: BN-apply + QKV via HMMA (fp16) ----------
__global__ __launch_bounds__(128) void qkv_kernel(
    const float* __restrict__ x,
    const float* __restrict__ wq, const float* __restrict__ bq,
    const float* __restrict__ wk, const float* __restrict__ bk,
    const float* __restrict__ wv, const float* __restrict__ bv) {
    __shared__ __align__(16) char sX[128 * 128];
    __shared__ __align__(16) char sW[3][64 * 128];
    int t = threadIdx.x, wid = t >> 5, l = t & 31;
    int n = blockIdx.y;
    int p0 = blockIdx.x * 128;
    uint32_t sXa = smem_u32(sX);

    {
        const float* xb = x + (size_t)n * C * HW + p0 + t;
        int r7 = t & 7;
#pragma unroll
        for (int cp = 0; cp < 32; cp++) {
            int c0 = 2 * cp;
            float v0 = xb[(size_t)c0 * HW] * g_scale[c0] + g_shift[c0];
            float v1 = xb[(size_t)(c0 + 1) * HW] * g_scale[c0 + 1] + g_shift[c0 + 1];
            uint32_t pk = packhf(v0, v1);
            uint32_t off = ((uint32_t)(((c0 >> 3) ^ r7) << 4)) + (uint32_t)((c0 & 7) * 2);
            *reinterpret_cast<uint32_t*>(&((char*)sX)[t * 128 + off]) = pk;
        }
    }
    {
        const float* ws[3] = {wq, wk, wv};
#pragma unroll
        for (int w = 0; w < 3; w++) {
            const float* wp = ws[w];
#pragma unroll
            for (int i = 0; i < 16; i++) {
                int idx = t + i * 128;
                int o = idx >> 5, cp = idx & 31, c0 = 2 * cp;
                float2 wv2 = *reinterpret_cast<const float2*>(wp + o * 64 + c0);
                uint32_t pk = packhf(wv2.x, wv2.y);
                uint32_t off = ((uint32_t)(((c0 >> 3) ^ (o & 7)) << 4)) + (uint32_t)((c0 & 7) * 2);
                *reinterpret_cast<uint32_t*>(&sW[w][o * 128 + off]) = pk;
            }
        }
    }
    __syncthreads();

    uint32_t A[2][4][4];
    {
        int arow = (l & 7) + ((l >> 3) & 1) * 8;
        int l7 = l & 7;
#pragma unroll
        for (int mt2 = 0; mt2 < 2; mt2++) {
            int m0 = (wid * 2 + mt2) * 16;
#pragma unroll
            for (int kt = 0; kt < 4; kt++) {
                uint32_t chunk = (uint32_t)((kt * 2 + (l >> 4)) ^ l7);
                ldsm4(A[mt2][kt], sXa + (uint32_t)(m0 + arow) * 128 + (chunk << 4));
            }
        }
    }

    const float* biases[3] = {bq, bk, bv};
    __half* outs[3] = {g_Q + (size_t)n * HW * C + (size_t)p0 * C,
                       g_Kb + (size_t)n * HW * C + (size_t)p0 * C,
                       g_V + (size_t)n * HW * C + (size_t)p0 * C};
    float scales[3] = {QSCALE, 1.f, 1.f};

    int brow = l & 7;
    uint32_t bx0 = (uint32_t)(((0 + (l >> 3)) ^ brow) << 4);
    uint32_t bx4 = (uint32_t)(((4 + (l >> 3)) ^ brow) << 4);

#pragma unroll
    for (int w = 0; w < 3; w++) {
        uint32_t sWa = smem_u32(sW[w]);
        float acc[2][8][4];
#pragma unroll
        for (int a = 0; a < 2; a++)
#pragma unroll
            for (int b = 0; b < 8; b++)
#pragma unroll
                for (int cc = 0; cc < 4; cc++) acc[a][b][cc] = 0.f;

#pragma unroll
        for (int nt = 0; nt < 8; nt++) {
            uint32_t base = sWa + (uint32_t)(nt * 8 + brow) * 128;
            uint32_t B[8];
            ldsm4(B, base + bx0);
            ldsm4(B + 4, base + bx4);
#pragma unroll
            for (int mt2 = 0; mt2 < 2; mt2++) {
                mma_f32f16(acc[mt2][nt], A[mt2][0], B[0], B[1]);
                mma_f32f16(acc[mt2][nt], A[mt2][1], B[2], B[3]);
                mma_f32f16(acc[mt2][nt], A[mt2][2], B[4], B[5]);
                mma_f32f16(acc[mt2][nt], A[mt2][3], B[6], B[7]);
            }
        }
        const float* bias = biases[w];
        float s = scales[w];
        __half* op = outs[w];
#pragma unroll
        for (int nt = 0; nt < 8; nt++) {
            int col = nt * 8 + (l & 3) * 2;
            float2 bb = *reinterpret_cast<const float2*>(bias + col);
#pragma unroll
            for (int mt2 = 0; mt2 < 2; mt2++) {
                int row0 = (wid * 2 + mt2) * 16 + (l >> 2);
                uint32_t pk0 = packhf((acc[mt2][nt][0] + bb.x) * s, (acc[mt2][nt][1] + bb.y) * s);
                uint32_t pk1 = packhf((acc[mt2][nt][2] + bb.x) * s, (acc[mt2][nt][3] + bb.y) * s);
                *reinterpret_cast<uint32_t*>(op + (size_t)row0 * C + col) = pk0;
                *reinterpret_cast<uint32_t*>(op + (size_t)(row0 + 8) * C + col) = pk1;
            }
        }
    }
}

// ---------- kernel 3: flash attention (fp16 pipeline, MMA row-sums) ----------
constexpr int ROWB = 144;

__global__ __launch_bounds__(128) void attn_kernel() {
    __shared__ __align__(16) char sK[2][KT * ROWB];
    __shared__ __align__(16) char sV[2][KT * ROWB];
    int t = threadIdx.x, wid = t >> 5, lane = t & 31;
    int n = blockIdx.y, qt = blockIdx.x;
    int qrow0 = qt * QT + wid * 32;
    int m = lane >> 2;
    int qp = (lane & 3) * 2;

    const __half* Kg = g_Kb + (size_t)n * HW * C;
    const __half* Vg = g_V + (size_t)n * HW * C;

    uint32_t lds_off = (uint32_t)((lane & 7) * ROWB + (lane >> 3) * 16);
    uint32_t ldt_off = (uint32_t)(((lane & 7) + ((lane >> 3) & 1) * 8) * ROWB + (lane >> 4) * 16);
    uint32_t sKa = smem_u32(sK);
    uint32_t sVa = smem_u32(sV);

    uint32_t qa[2][4][4];
#pragma unroll
    for (int mt = 0; mt < 2; mt++) {
        const __half* Qb = g_Q + ((size_t)n * HW + qrow0 + mt * 16) * C;
#pragma unroll
        for (int kb = 0; kb < 4; kb++) {
            qa[mt][kb][0] = *(const uint32_t*)(Qb + (size_t)m * C + kb * 16 + qp);
            qa[mt][kb][1] = *(const uint32_t*)(Qb + (size_t)(m + 8) * C + kb * 16 + qp);
            qa[mt][kb][2] = *(const uint32_t*)(Qb + (size_t)m * C + kb * 16 + 8 + qp);
            qa[mt][kb][3] = *(const uint32_t*)(Qb + (size_t)(m + 8) * C + kb * 16 + 8 + qp);
        }
    }

    float oacc[2][8][4];
#pragma unroll
    for (int mt = 0; mt < 2; mt++)
#pragma unroll
        for (int i = 0; i < 8; i++)
#pragma unroll
            for (int j = 0; j < 4; j++) oacc[mt][i][j] = 0.f;
    float lacc[2][4];
#pragma unroll
    for (int mt = 0; mt < 2; mt++)
#pragma unroll
        for (int j = 0; j < 4; j++) lacc[mt][j] = 0.f;

    auto prefetch = [&](int b, int kt) {
#pragma unroll
        for (int rr = 0; rr < 4; rr++) {
            int ch = t + rr * 128;
            int row = ch >> 3, col = ch & 7;
            cp_async16(sKa + (uint32_t)(b * KT * ROWB + row * ROWB + col * 16),
                       Kg + ((size_t)(kt * KT + row)) * C + col * 8);
            cp_async16(sVa + (uint32_t)(b * KT * ROWB + row * ROWB + col * 16),
                       Vg + ((size_t)(kt * KT + row)) * C + col * 8);
        }
        cp_commit();
    };

    prefetch(0, 0);

    for (int kt = 0; kt < NKT; kt++) {
        asm volatile("cp.async.wait_group 0;");
        __syncthreads();
        if (kt + 1 < NKT) prefetch((kt + 1) & 1, kt + 1);

        uint32_t kb_a = sKa + (uint32_t)((kt & 1) * KT * ROWB) + lds_off;
        uint32_t vb_a = sVa + (uint32_t)((kt & 1) * KT * ROWB) + ldt_off;

        // MMA1 (fp16 accum, packed) + ex2.f16x2 -> P fragments; rowsum via ones-MMA
        uint32_t pa[2][4][4];
#pragma unroll
        for (int kc = 0; kc < 4; kc++) {
            uint32_t s16[2][2][2];     // [mt][ntile-in-pair][2 packed regs]
#pragma unroll
            for (int j = 0; j < 2; j++) {
                int nt = kc * 2 + j;
                uint32_t B[8];
                ldsm4(B, kb_a + nt * 8 * ROWB);
                ldsm4(B + 4, kb_a + nt * 8 * ROWB + 64);
#pragma unroll
                for (int mt = 0; mt < 2; mt++) {
                    s16[mt][j][0] = 0u; s16[mt][j][1] = 0u;
                    mma_f16acc(s16[mt][j], qa[mt][0], B[0], B[1]);
                    mma_f16acc(s16[mt][j], qa[mt][1], B[2], B[3]);
                    mma_f16acc(s16[mt][j], qa[mt][2], B[4], B[5]);
                    mma_f16acc(s16[mt][j], qa[mt][3], B[6], B[7]);
                }
            }
#pragma unroll
            for (int mt = 0; mt < 2; mt++) {
                pa[mt][kc][0] = h2ex2(s16[mt][0][0]);
                pa[mt][kc][1] = h2ex2(s16[mt][0][1]);
                pa[mt][kc][2] = h2ex2(s16[mt][1][0]);
                pa[mt][kc][3] = h2ex2(s16[mt][1][1]);
                // exact fp32 row-sums: P(kc) x ones (N=8)
                mma_f32f16(lacc[mt], pa[mt][kc], ONE2, ONE2);
            }
        }

        // MMA2: O += P * V
#pragma unroll
        for (int np = 0; np < 4; np++) {
#pragma unroll
            for (int kc = 0; kc < 4; kc++) {
                uint32_t B[4];
                ldsm4t(B, vb_a + (uint32_t)(kc * 16 * ROWB + np * 32));
#pragma unroll
                for (int mt = 0; mt < 2; mt++) {
                    mma_f32f16(oacc[mt][2 * np], pa[mt][kc], B[0], B[1]);
                    mma_f32f16(oacc[mt][2 * np + 1], pa[mt][kc], B[2], B[3]);
                }
            }
        }
    }

    // lacc[mt][0] = rowsum(row m), lacc[mt][2] = rowsum(row m+8) — identical in all quad lanes
#pragma unroll
    for (int mt = 0; mt < 2; mt++) {
        float inv0 = 1.f / lacc[mt][0];
        float inv1 = 1.f / lacc[mt][2];

        float* orow0 = g_O + ((size_t)n * HW + qrow0 + mt * 16 + m) * C;
        float* orow1 = orow0 + 8 * C;
#pragma unroll
        for (int ct = 0; ct < 8; ct++) {
            int col = ct * 8 + qp;
            float2 v0 = make_float2(oacc[mt][ct][0] * inv0, oacc[mt][ct][1] * inv0);
            float2 v1 = make_float2(oacc[mt][ct][2] * inv1, oacc[mt][ct][3] * inv1);
            *reinterpret_cast<float2*>(orow0 + col) = v0;
            *reinterpret_cast<float2*>(orow1 + col) = v1;
        }
    }
}

// ---------- kernel 4: output conv via HMMA (fp16) + residual ----------
__global__ __launch_bounds__(128) void out_kernel(
    const float* __restrict__ x, const float* __restrict__ wo,
    const float* __restrict__ bo, float* __restrict__ out) {
    __shared__ __align__(16) char smem[24576];
    int t = threadIdx.x, wid = t >> 5, l = t & 31;
    int n = blockIdx.y;
    int p0 = blockIdx.x * 128;
    uint32_t sOa = smem_u32(smem);
    uint32_t sWa = sOa + 16384;

    {
        const float* Ob = g_O + (size_t)n * C * HW + p0 + t;
        int r7 = t & 7;
#pragma unroll
        for (int cp = 0; cp < 32; cp++) {
            int c0 = 2 * cp;
            float v0 = Ob[(size_t)c0 * HW];
            float v1 = Ob[(size_t)(c0 + 1) * HW];
            uint32_t pk = packhf(v0, v1);
            uint32_t off = ((uint32_t)(((c0 >> 3) ^ r7) << 4)) + (uint32_t)((c0 & 7) * 2);
            *reinterpret_cast<uint32_t*>(&smem[t * 128 + off]) = pk;
        }
    }
#pragma unroll
    for (int i = 0; i < 16; i++) {
        int idx = t + i * 128;
        int o = idx >> 5, cp = idx & 31, c0 = 2 * cp;
        float2 wv2 = *reinterpret_cast<const float2*>(wo + o * 64 + c0);
        uint32_t pk = packhf(wv2.x, wv2.y);
        uint32_t off = ((uint32_t)(((c0 >> 3) ^ (o & 7)) << 4)) + (uint32_t)((c0 & 7) * 2);
        *reinterpret_cast<uint32_t*>(&smem[16384 + o * 128 + off]) = pk;
    }
    __syncthreads();

    uint32_t A[2][4][4];
    {
        int arow = (l & 7) + ((l >> 3) & 1) * 8;
        int l7 = l & 7;
#pragma unroll
        for (int mt2 = 0; mt2 < 2; mt2++) {
            int m0 = (wid * 2 + mt2) * 16;
#pragma unroll
            for (int kt = 0; kt < 4; kt++) {
                uint32_t chunk = (uint32_t)((kt * 2 + (l >> 4)) ^ l7);
                ldsm4(A[mt2][kt], sOa + (uint32_t)(m0 + arow) * 128 + (chunk << 4));
            }
        }
    }

    int brow = l & 7;
    uint32_t bx0 = (uint32_t)(((0 + (l >> 3)) ^ brow) << 4);
    uint32_t bx4 = (uint32_t)(((4 + (l >> 3)) ^ brow) << 4);

    float acc[2][8][4];
#pragma unroll
    for (int a = 0; a < 2; a++)
#pragma unroll
        for (int b = 0; b < 8; b++)
#pragma unroll
            for (int cc = 0; cc < 4; cc++) acc[a][b][cc] = 0.f;

#pragma unroll
    for (int nt = 0; nt < 8; nt++) {
        uint32_t base = sWa + (uint32_t)(nt * 8 + brow) * 128;
        uint32_t B[8];
        ldsm4(B, base + bx0);
        ldsm4(B + 4, base + bx4);
#pragma unroll
        for (int mt2 = 0; mt2 < 2; mt2++) {
            mma_f32f16(acc[mt2][nt], A[mt2][0], B[0], B[1]);
            mma_f32f16(acc[mt2][nt], A[mt2][1], B[2], B[3]);
            mma_f32f16(acc[mt2][nt], A[mt2][2], B[4], B[5]);
            mma_f32f16(acc[mt2][nt], A[mt2][3], B[6], B[7]);
        }
    }
    __syncthreads();

    // write sP[o][p] fp16 (pitch 264B), bias added
#pragma unroll
    for (int nt = 0; nt < 8; nt++) {
        int col = nt * 8 + (l & 3) * 2;
        float2 bb = *reinterpret_cast<const float2*>(bo + col);
#pragma unroll
        for (int mt2 = 0; mt2 < 2; mt2++) {
            int row0 = (wid * 2 + mt2) * 16 + (l >> 2);
            *reinterpret_cast<__half*>(&smem[col * 264 + row0 * 2])       = __float2half(acc[mt2][nt][0] + bb.x);
            *reinterpret_cast<__half*>(&smem[(col + 1) * 264 + row0 * 2]) = __float2half(acc[mt2][nt][1] + bb.y);
            *reinterpret_cast<__half*>(&smem[col * 264 + (row0 + 8) * 2])       = __float2half(acc[mt2][nt][2] + bb.x);
            *reinterpret_cast<__half*>(&smem[(col + 1) * 264 + (row0 + 8) * 2]) = __float2half(acc[mt2][nt][3] + bb.y);
        }
    }
    __syncthreads();

#pragma unroll
    for (int oo = 0; oo < 16; oo++) {
        int o = wid * 16 + oo;
        uint2 pk = *reinterpret_cast<const uint2*>(&smem[o * 264 + l * 8]);
        __half2 b01 = *reinterpret_cast<__half2*>(&pk.x);
        __half2 b23 = *reinterpret_cast<__half2*>(&pk.y);
        const float* xb = x + ((size_t)n * C + o) * HW + p0 + l * 4;
        float4 xv = *reinterpret_cast<const float4*>(xb);
        float4 r;
        r.x = __half2float(b01.x) + xv.x;
        r.y = __half2float(b01.y) + xv.y;
        r.z = __half2float(b23.x) + xv.z;
        r.w = __half2float(b23.y) + xv.w;
        *reinterpret_cast<float4*>(out + ((size_t)n * C + o) * HW + p0 + l * 4) = r;
    }
}

extern "C" void kernel_launch(void* const* d_in, const int* in_sizes, int n_in,
                              void* d_out, int out_size) {
    const float* x     = (const float*)d_in[0];
    const float* gamma = (const float*)d_in[1];
    const float* beta  = (const float*)d_in[2];
    const float* wq    = (const float*)d_in[3];
    const float* bq    = (const float*)d_in[4];
    const float* wk    = (const float*)d_in[5];
    const float* bk    = (const float*)d_in[6];
    const float* wv    = (const float*)d_in[7];
    const float* bv    = (const float*)d_in[8];
    const float* wo    = (const float*)d_in[9];
    const float* bo    = (const float*)d_in[10];
    float* out = (float*)d_out;

    bn_part<<<512, 256>>>(x);
    bn_fin<<<1, 64>>>(gamma, beta);
    qkv_kernel<<<dim3(HW / 128, NB), 128>>>(x, wq, bq, wk, bk, wv, bv);
    attn_kernel<<<dim3(HW / QT, NB), 128>>>();
    out_kernel<<<dim3(HW / 128, NB), 128>>>(x, wo, bo, out);
}

// round 15
// speedup vs baseline: 1.1003x; 1.1003x over previous
#include <cuda_runtime.h>
#include <cuda_fp16.h>
#include <cstdint>

constexpr int NB = 8, C = 64, HW = 4096;
constexpr int QT = 128;                // q rows per CTA (32 per warp, 2 mtiles)
constexpr int KT = 64;                 // keys per iteration
constexpr int NKT = HW / KT;           // 64
constexpr float EPS_BN = 1e-5f;
constexpr float QSCALE = 0.125f * 1.4426950408889634f;  // (1/sqrt(64)) * log2(e)
constexpr uint32_t ONE2 = 0x3C003C00u; // half2(1,1)

__device__ __align__(256) float g_scale[C];
__device__ __align__(256) float g_shift[C];
__device__ __align__(256) float g_ps[512];
__device__ __align__(256) float g_pq[512];
__device__ __align__(256) __half g_Q[(size_t)NB * HW * C];   // [n,i,c] pre-scaled
__device__ __align__(256) __half g_Kb[(size_t)NB * HW * C];  // [n,j,c]
__device__ __align__(256) __half g_V[(size_t)NB * HW * C];   // [n,j,c]
__device__ __align__(256) float g_O[(size_t)NB * HW * C];    // [n,i,c]

// ---------- helpers ----------
__device__ __forceinline__ uint32_t smem_u32(const void* p) {
    uint32_t a;
    asm("{ .reg .u64 t; cvta.to.shared.u64 t, %1; cvt.u32.u64 %0, t; }" : "=r"(a) : "l"(p));
    return a;
}
__device__ __forceinline__ void cp_async16(uint32_t s, const void* g) {
    asm volatile("cp.async.cg.shared.global [%0], [%1], 16;" :: "r"(s), "l"(g));
}
__device__ __forceinline__ void cp_commit() { asm volatile("cp.async.commit_group;"); }

__device__ __forceinline__ void mma_f32f16(float* d, const uint32_t* a, uint32_t b0, uint32_t b1) {
    asm volatile(
        "mma.sync.aligned.m16n8k16.row.col.f32.f16.f16.f32 "
        "{%0,%1,%2,%3}, {%4,%5,%6,%7}, {%8,%9}, {%0,%1,%2,%3};"
        : "+f"(d[0]), "+f"(d[1]), "+f"(d[2]), "+f"(d[3])
        : "r"(a[0]), "r"(a[1]), "r"(a[2]), "r"(a[3]), "r"(b0), "r"(b1));
}
__device__ __forceinline__ void mma_f16acc(uint32_t* d, const uint32_t* a, uint32_t b0, uint32_t b1) {
    asm volatile(
        "mma.sync.aligned.m16n8k16.row.col.f16.f16.f16.f16 "
        "{%0,%1}, {%2,%3,%4,%5}, {%6,%7}, {%0,%1};"
        : "+r"(d[0]), "+r"(d[1])
        : "r"(a[0]), "r"(a[1]), "r"(a[2]), "r"(a[3]), "r"(b0), "r"(b1));
}
__device__ __forceinline__ uint32_t h2ex2(uint32_t x) {
    uint32_t y; asm("ex2.approx.f16x2 %0, %1;" : "=r"(y) : "r"(x)); return y;
}
__device__ __forceinline__ void ldsm4(uint32_t* r, uint32_t addr) {
    asm volatile("ldmatrix.sync.aligned.m8n8.x4.shared.b16 {%0,%1,%2,%3}, [%4];"
        : "=r"(r[0]), "=r"(r[1]), "=r"(r[2]), "=r"(r[3]) : "r"(addr));
}
__device__ __forceinline__ void ldsm4t(uint32_t* r, uint32_t addr) {
    asm volatile("ldmatrix.sync.aligned.m8n8.x4.trans.shared.b16 {%0,%1,%2,%3}, [%4];"
        : "=r"(r[0]), "=r"(r[1]), "=r"(r[2]), "=r"(r[3]) : "r"(addr));
}
__device__ __forceinline__ uint32_t packhf(float a, float b) {
    __half2 t = __floats2half2_rn(a, b);
    return *reinterpret_cast<uint32_t*>(&t);
}

// ---------- kernel 1a: BN partial sums ----------
__global__ __launch_bounds__(256) void bn_part(const float* __restrict__ x) {
    int c = blockIdx.x >> 3, s = blockIdx.x & 7, t = threadIdx.x;
    const float* p = x + ((size_t)s * C + c) * HW;
    float sm = 0.f, sq = 0.f;
#pragma unroll
    for (int i = 0; i < HW / 256; i++) { float v = p[t + i * 256]; sm += v; sq += v * v; }
    __shared__ float rs[256], rq[256];
    rs[t] = sm; rq[t] = sq; __syncthreads();
    for (int o = 128; o > 0; o >>= 1) {
        if (t < o) { rs[t] += rs[t + o]; rq[t] += rq[t + o]; }
        __syncthreads();
    }
    if (t == 0) { g_ps[c * 8 + s] = rs[0]; g_pq[c * 8 + s] = rq[0]; }
}

// ---------- kernel 1b: BN finalize ----------
__global__ void bn_fin(const float* __restrict__ gamma, const float* __restrict__ beta) {
    int c = threadIdx.x;
    float sm = 0.f, sq = 0.f;
#pragma unroll
    for (int k = 0; k < 8; k++) { sm += g_ps[c * 8 + k]; sq += g_pq[c * 8 + k]; }
    float inv = 1.0f / (float)(NB * HW);
    float mean = sm * inv;
    float var = sq * inv - mean * mean;
    float sc = rsqrtf(var + EPS_BN) * gamma[c];
    g_scale[c] = sc;
    g_shift[c] = beta[c] - mean * sc;
}

// ---------- kernel 2: BN-apply + QKV via HMMA (fp16) ----------
__global__ __launch_bounds__(128) void qkv_kernel(
    const float* __restrict__ x,
    const float* __restrict__ wq, const float* __restrict__ bq,
    const float* __restrict__ wk, const float* __restrict__ bk,
    const float* __restrict__ wv, const float* __restrict__ bv) {
    __shared__ __align__(16) char sX[128 * 128];
    __shared__ __align__(16) char sW[3][64 * 128];
    int t = threadIdx.x, wid = t >> 5, l = t & 31;
    int n = blockIdx.y;
    int p0 = blockIdx.x * 128;
    uint32_t sXa = smem_u32(sX);

    {
        const float* xb = x + (size_t)n * C * HW + p0 + t;
        int r7 = t & 7;
#pragma unroll
        for (int cp = 0; cp < 32; cp++) {
            int c0 = 2 * cp;
            float v0 = xb[(size_t)c0 * HW] * g_scale[c0] + g_shift[c0];
            float v1 = xb[(size_t)(c0 + 1) * HW] * g_scale[c0 + 1] + g_shift[c0 + 1];
            uint32_t pk = packhf(v0, v1);
            uint32_t off = ((uint32_t)(((c0 >> 3) ^ r7) << 4)) + (uint32_t)((c0 & 7) * 2);
            *reinterpret_cast<uint32_t*>(&((char*)sX)[t * 128 + off]) = pk;
        }
    }
    {
        const float* ws[3] = {wq, wk, wv};
#pragma unroll
        for (int w = 0; w < 3; w++) {
            const float* wp = ws[w];
#pragma unroll
            for (int i = 0; i < 16; i++) {
                int idx = t + i * 128;
                int o = idx >> 5, cp = idx & 31, c0 = 2 * cp;
                float2 wv2 = *reinterpret_cast<const float2*>(wp + o * 64 + c0);
                uint32_t pk = packhf(wv2.x, wv2.y);
                uint32_t off = ((uint32_t)(((c0 >> 3) ^ (o & 7)) << 4)) + (uint32_t)((c0 & 7) * 2);
                *reinterpret_cast<uint32_t*>(&sW[w][o * 128 + off]) = pk;
            }
        }
    }
    __syncthreads();

    uint32_t A[2][4][4];
    {
        int arow = (l & 7) + ((l >> 3) & 1) * 8;
        int l7 = l & 7;
#pragma unroll
        for (int mt2 = 0; mt2 < 2; mt2++) {
            int m0 = (wid * 2 + mt2) * 16;
#pragma unroll
            for (int kt = 0; kt < 4; kt++) {
                uint32_t chunk = (uint32_t)((kt * 2 + (l >> 4)) ^ l7);
                ldsm4(A[mt2][kt], sXa + (uint32_t)(m0 + arow) * 128 + (chunk << 4));
            }
        }
    }

    const float* biases[3] = {bq, bk, bv};
    __half* outs[3] = {g_Q + (size_t)n * HW * C + (size_t)p0 * C,
                       g_Kb + (size_t)n * HW * C + (size_t)p0 * C,
                       g_V + (size_t)n * HW * C + (size_t)p0 * C};
    float scales[3] = {QSCALE, 1.f, 1.f};

    int brow = l & 7;
    uint32_t bx0 = (uint32_t)(((0 + (l >> 3)) ^ brow) << 4);
    uint32_t bx4 = (uint32_t)(((4 + (l >> 3)) ^ brow) << 4);

#pragma unroll
    for (int w = 0; w < 3; w++) {
        uint32_t sWa = smem_u32(sW[w]);
        float acc[2][8][4];
#pragma unroll
        for (int a = 0; a < 2; a++)
#pragma unroll
            for (int b = 0; b < 8; b++)
#pragma unroll
                for (int cc = 0; cc < 4; cc++) acc[a][b][cc] = 0.f;

#pragma unroll
        for (int nt = 0; nt < 8; nt++) {
            uint32_t base = sWa + (uint32_t)(nt * 8 + brow) * 128;
            uint32_t B[8];
            ldsm4(B, base + bx0);
            ldsm4(B + 4, base + bx4);
#pragma unroll
            for (int mt2 = 0; mt2 < 2; mt2++) {
                mma_f32f16(acc[mt2][nt], A[mt2][0], B[0], B[1]);
                mma_f32f16(acc[mt2][nt], A[mt2][1], B[2], B[3]);
                mma_f32f16(acc[mt2][nt], A[mt2][2], B[4], B[5]);
                mma_f32f16(acc[mt2][nt], A[mt2][3], B[6], B[7]);
            }
        }
        const float* bias = biases[w];
        float s = scales[w];
        __half* op = outs[w];
#pragma unroll
        for (int nt = 0; nt < 8; nt++) {
            int col = nt * 8 + (l & 3) * 2;
            float2 bb = *reinterpret_cast<const float2*>(bias + col);
#pragma unroll
            for (int mt2 = 0; mt2 < 2; mt2++) {
                int row0 = (wid * 2 + mt2) * 16 + (l >> 2);
                uint32_t pk0 = packhf((acc[mt2][nt][0] + bb.x) * s, (acc[mt2][nt][1] + bb.y) * s);
                uint32_t pk1 = packhf((acc[mt2][nt][2] + bb.x) * s, (acc[mt2][nt][3] + bb.y) * s);
                *reinterpret_cast<uint32_t*>(op + (size_t)row0 * C + col) = pk0;
                *reinterpret_cast<uint32_t*>(op + (size_t)(row0 + 8) * C + col) = pk1;
            }
        }
    }
}

// ---------- kernel 3: flash attention (fp16, ILP-restructured inner loops) ----------
constexpr int ROWB = 144;

__global__ __launch_bounds__(128) void attn_kernel() {
    __shared__ __align__(16) char sK[2][KT * ROWB];
    __shared__ __align__(16) char sV[2][KT * ROWB];
    int t = threadIdx.x, wid = t >> 5, lane = t & 31;
    int n = blockIdx.y, qt = blockIdx.x;
    int qrow0 = qt * QT + wid * 32;
    int m = lane >> 2;
    int qp = (lane & 3) * 2;

    const __half* Kg = g_Kb + (size_t)n * HW * C;
    const __half* Vg = g_V + (size_t)n * HW * C;

    uint32_t lds_off = (uint32_t)((lane & 7) * ROWB + (lane >> 3) * 16);
    uint32_t ldt_off = (uint32_t)(((lane & 7) + ((lane >> 3) & 1) * 8) * ROWB + (lane >> 4) * 16);
    uint32_t sKa = smem_u32(sK);
    uint32_t sVa = smem_u32(sV);

    uint32_t qa[2][4][4];
#pragma unroll
    for (int mt = 0; mt < 2; mt++) {
        const __half* Qb = g_Q + ((size_t)n * HW + qrow0 + mt * 16) * C;
#pragma unroll
        for (int kb = 0; kb < 4; kb++) {
            qa[mt][kb][0] = *(const uint32_t*)(Qb + (size_t)m * C + kb * 16 + qp);
            qa[mt][kb][1] = *(const uint32_t*)(Qb + (size_t)(m + 8) * C + kb * 16 + qp);
            qa[mt][kb][2] = *(const uint32_t*)(Qb + (size_t)m * C + kb * 16 + 8 + qp);
            qa[mt][kb][3] = *(const uint32_t*)(Qb + (size_t)(m + 8) * C + kb * 16 + 8 + qp);
        }
    }

    float oacc[2][8][4];
#pragma unroll
    for (int mt = 0; mt < 2; mt++)
#pragma unroll
        for (int i = 0; i < 8; i++)
#pragma unroll
            for (int j = 0; j < 4; j++) oacc[mt][i][j] = 0.f;
    float lacc[2][4];
#pragma unroll
    for (int mt = 0; mt < 2; mt++)
#pragma unroll
        for (int j = 0; j < 4; j++) lacc[mt][j] = 0.f;

    auto prefetch = [&](int b, int kt) {
#pragma unroll
        for (int rr = 0; rr < 4; rr++) {
            int ch = t + rr * 128;
            int row = ch >> 3, col = ch & 7;
            cp_async16(sKa + (uint32_t)(b * KT * ROWB + row * ROWB + col * 16),
                       Kg + ((size_t)(kt * KT + row)) * C + col * 8);
            cp_async16(sVa + (uint32_t)(b * KT * ROWB + row * ROWB + col * 16),
                       Vg + ((size_t)(kt * KT + row)) * C + col * 8);
        }
        cp_commit();
    };

    prefetch(0, 0);

    for (int kt = 0; kt < NKT; kt++) {
        asm volatile("cp.async.wait_group 0;");
        __syncthreads();
        if (kt + 1 < NKT) prefetch((kt + 1) & 1, kt + 1);

        uint32_t kb_a = sKa + (uint32_t)((kt & 1) * KT * ROWB) + lds_off;
        uint32_t vb_a = sVa + (uint32_t)((kt & 1) * KT * ROWB) + ldt_off;

        // ---- MMA1: K-step-outer, 4 independent fp16-accum chains ----
        uint32_t pa[2][4][4];
#pragma unroll
        for (int kc = 0; kc < 4; kc++) {
            uint32_t B[16];
            ldsm4(B,      kb_a + (kc * 2)     * 8 * ROWB);
            ldsm4(B + 4,  kb_a + (kc * 2)     * 8 * ROWB + 64);
            ldsm4(B + 8,  kb_a + (kc * 2 + 1) * 8 * ROWB);
            ldsm4(B + 12, kb_a + (kc * 2 + 1) * 8 * ROWB + 64);
            uint32_t s00[2] = {0u, 0u}, s10[2] = {0u, 0u};
            uint32_t s01[2] = {0u, 0u}, s11[2] = {0u, 0u};
#pragma unroll
            for (int kb = 0; kb < 4; kb++) {
                mma_f16acc(s00, qa[0][kb], B[2 * kb], B[2 * kb + 1]);
                mma_f16acc(s10, qa[1][kb], B[2 * kb], B[2 * kb + 1]);
                mma_f16acc(s01, qa[0][kb], B[8 + 2 * kb], B[8 + 2 * kb + 1]);
                mma_f16acc(s11, qa[1][kb], B[8 + 2 * kb], B[8 + 2 * kb + 1]);
            }
            pa[0][kc][0] = h2ex2(s00[0]);
            pa[0][kc][1] = h2ex2(s00[1]);
            pa[0][kc][2] = h2ex2(s01[0]);
            pa[0][kc][3] = h2ex2(s01[1]);
            pa[1][kc][0] = h2ex2(s10[0]);
            pa[1][kc][1] = h2ex2(s10[1]);
            pa[1][kc][2] = h2ex2(s11[0]);
            pa[1][kc][3] = h2ex2(s11[1]);
            mma_f32f16(lacc[0], pa[0][kc], ONE2, ONE2);
            mma_f32f16(lacc[1], pa[1][kc], ONE2, ONE2);
        }

        // ---- MMA2: kc-outer, 16 independent accumulators per kc ----
#pragma unroll
        for (int kc = 0; kc < 4; kc++) {
            uint32_t B[16];
#pragma unroll
            for (int np = 0; np < 4; np++)
                ldsm4t(B + 4 * np, vb_a + (uint32_t)(kc * 16 * ROWB + np * 32));
#pragma unroll
            for (int np = 0; np < 4; np++) {
#pragma unroll
                for (int mt = 0; mt < 2; mt++) {
                    mma_f32f16(oacc[mt][2 * np],     pa[mt][kc], B[4 * np],     B[4 * np + 1]);
                    mma_f32f16(oacc[mt][2 * np + 1], pa[mt][kc], B[4 * np + 2], B[4 * np + 3]);
                }
            }
        }
    }

    // lacc[mt][0] = rowsum(row m), lacc[mt][2] = rowsum(row m+8)
#pragma unroll
    for (int mt = 0; mt < 2; mt++) {
        float inv0 = 1.f / lacc[mt][0];
        float inv1 = 1.f / lacc[mt][2];

        float* orow0 = g_O + ((size_t)n * HW + qrow0 + mt * 16 + m) * C;
        float* orow1 = orow0 + 8 * C;
#pragma unroll
        for (int ct = 0; ct < 8; ct++) {
            int col = ct * 8 + qp;
            float2 v0 = make_float2(oacc[mt][ct][0] * inv0, oacc[mt][ct][1] * inv0);
            float2 v1 = make_float2(oacc[mt][ct][2] * inv1, oacc[mt][ct][3] * inv1);
            *reinterpret_cast<float2*>(orow0 + col) = v0;
            *reinterpret_cast<float2*>(orow1 + col) = v1;
        }
    }
}

// ---------- kernel 4: output conv via HMMA (fp16) + residual ----------
__global__ __launch_bounds__(128) void out_kernel(
    const float* __restrict__ x, const float* __restrict__ wo,
    const float* __restrict__ bo, float* __restrict__ out) {
    __shared__ __align__(16) char smem[24576];
    int t = threadIdx.x, wid = t >> 5, l = t & 31;
    int n = blockIdx.y;
    int p0 = blockIdx.x * 128;
    uint32_t sOa = smem_u32(smem);
    uint32_t sWa = sOa + 16384;

    {
        const float* Ob = g_O + (size_t)n * C * HW + p0 + t;
        int r7 = t & 7;
#pragma unroll
        for (int cp = 0; cp < 32; cp++) {
            int c0 = 2 * cp;
            float v0 = Ob[(size_t)c0 * HW];
            float v1 = Ob[(size_t)(c0 + 1) * HW];
            uint32_t pk = packhf(v0, v1);
            uint32_t off = ((uint32_t)(((c0 >> 3) ^ r7) << 4)) + (uint32_t)((c0 & 7) * 2);
            *reinterpret_cast<uint32_t*>(&smem[t * 128 + off]) = pk;
        }
    }
#pragma unroll
    for (int i = 0; i < 16; i++) {
        int idx = t + i * 128;
        int o = idx >> 5, cp = idx & 31, c0 = 2 * cp;
        float2 wv2 = *reinterpret_cast<const float2*>(wo + o * 64 + c0);
        uint32_t pk = packhf(wv2.x, wv2.y);
        uint32_t off = ((uint32_t)(((c0 >> 3) ^ (o & 7)) << 4)) + (uint32_t)((c0 & 7) * 2);
        *reinterpret_cast<uint32_t*>(&smem[16384 + o * 128 + off]) = pk;
    }
    __syncthreads();

    uint32_t A[2][4][4];
    {
        int arow = (l & 7) + ((l >> 3) & 1) * 8;
        int l7 = l & 7;
#pragma unroll
        for (int mt2 = 0; mt2 < 2; mt2++) {
            int m0 = (wid * 2 + mt2) * 16;
#pragma unroll
            for (int kt = 0; kt < 4; kt++) {
                uint32_t chunk = (uint32_t)((kt * 2 + (l >> 4)) ^ l7);
                ldsm4(A[mt2][kt], sOa + (uint32_t)(m0 + arow) * 128 + (chunk << 4));
            }
        }
    }

    int brow = l & 7;
    uint32_t bx0 = (uint32_t)(((0 + (l >> 3)) ^ brow) << 4);
    uint32_t bx4 = (uint32_t)(((4 + (l >> 3)) ^ brow) << 4);

    float acc[2][8][4];
#pragma unroll
    for (int a = 0; a < 2; a++)
#pragma unroll
        for (int b = 0; b < 8; b++)
#pragma unroll
            for (int cc = 0; cc < 4; cc++) acc[a][b][cc] = 0.f;

#pragma unroll
    for (int nt = 0; nt < 8; nt++) {
        uint32_t base = sWa + (uint32_t)(nt * 8 + brow) * 128;
        uint32_t B[8];
        ldsm4(B, base + bx0);
        ldsm4(B + 4, base + bx4);
#pragma unroll
        for (int mt2 = 0; mt2 < 2; mt2++) {
            mma_f32f16(acc[mt2][nt], A[mt2][0], B[0], B[1]);
            mma_f32f16(acc[mt2][nt], A[mt2][1], B[2], B[3]);
            mma_f32f16(acc[mt2][nt], A[mt2][2], B[4], B[5]);
            mma_f32f16(acc[mt2][nt], A[mt2][3], B[6], B[7]);
        }
    }
    __syncthreads();

#pragma unroll
    for (int nt = 0; nt < 8; nt++) {
        int col = nt * 8 + (l & 3) * 2;
        float2 bb = *reinterpret_cast<const float2*>(bo + col);
#pragma unroll
        for (int mt2 = 0; mt2 < 2; mt2++) {
            int row0 = (wid * 2 + mt2) * 16 + (l >> 2);
            *reinterpret_cast<__half*>(&smem[col * 264 + row0 * 2])       = __float2half(acc[mt2][nt][0] + bb.x);
            *reinterpret_cast<__half*>(&smem[(col + 1) * 264 + row0 * 2]) = __float2half(acc[mt2][nt][1] + bb.y);
            *reinterpret_cast<__half*>(&smem[col * 264 + (row0 + 8) * 2])       = __float2half(acc[mt2][nt][2] + bb.x);
            *reinterpret_cast<__half*>(&smem[(col + 1) * 264 + (row0 + 8) * 2]) = __float2half(acc[mt2][nt][3] + bb.y);
        }
    }
    __syncthreads();

#pragma unroll
    for (int oo = 0; oo < 16; oo++) {
        int o = wid * 16 + oo;
        uint2 pk = *reinterpret_cast<const uint2*>(&smem[o * 264 + l * 8]);
        __half2 b01 = *reinterpret_cast<__half2*>(&pk.x);
        __half2 b23 = *reinterpret_cast<__half2*>(&pk.y);
        const float* xb = x + ((size_t)n * C + o) * HW + p0 + l * 4;
        float4 xv = *reinterpret_cast<const float4*>(xb);
        float4 r;
        r.x = __half2float(b01.x) + xv.x;
        r.y = __half2float(b01.y) + xv.y;
        r.z = __half2float(b23.x) + xv.z;
        r.w = __half2float(b23.y) + xv.w;
        *reinterpret_cast<float4*>(out + ((size_t)n * C + o) * HW + p0 + l * 4) = r;
    }
}

extern "C" void kernel_launch(void* const* d_in, const int* in_sizes, int n_in,
                              void* d_out, int out_size) {
    const float* x     = (const float*)d_in[0];
    const float* gamma = (const float*)d_in[1];
    const float* beta  = (const float*)d_in[2];
    const float* wq    = (const float*)d_in[3];
    const float* bq    = (const float*)d_in[4];
    const float* wk    = (const float*)d_in[5];
    const float* bk    = (const float*)d_in[6];
    const float* wv    = (const float*)d_in[7];
    const float* bv    = (const float*)d_in[8];
    const float* wo    = (const float*)d_in[9];
    const float* bo    = (const float*)d_in[10];
    float* out = (float*)d_out;

    bn_part<<<512, 256>>>(x);
    bn_fin<<<1, 64>>>(gamma, beta);
    qkv_kernel<<<dim3(HW / 128, NB), 128>>>(x, wq, bq, wk, bk, wv, bv);
    attn_kernel<<<dim3(HW / QT, NB), 128>>>();
    out_kernel<<<dim3(HW / 128, NB), 128>>>(x, wo, bo, out);
}

// round 16
// speedup vs baseline: 1.1224x; 1.0201x over previous
#include <cuda_runtime.h>
#include <cuda_fp16.h>
#include <cstdint>

constexpr int NB = 8, C = 64, HW = 4096;
constexpr int QT = 128;                // q rows per CTA (32 per warp, 2 mtiles)
constexpr int KT = 64;                 // keys per iteration
constexpr int NKT = HW / KT;           // 64
constexpr float EPS_BN = 1e-5f;
constexpr float QSCALE = 0.125f * 1.4426950408889634f;  // (1/sqrt(64)) * log2(e)
constexpr uint32_t ONE2 = 0x3C003C00u; // half2(1,1)

__device__ __align__(256) float g_ps[512];
__device__ __align__(256) float g_pq[512];
__device__ __align__(256) __half g_Q[(size_t)NB * HW * C];   // [n,i,c] pre-scaled
__device__ __align__(256) __half g_Kb[(size_t)NB * HW * C];  // [n,j,c]
__device__ __align__(256) __half g_V[(size_t)NB * HW * C];   // [n,j,c]
__device__ __align__(256) float g_O[(size_t)NB * HW * C];    // [n,i,c]

// ---------- helpers ----------
__device__ __forceinline__ uint32_t smem_u32(const void* p) {
    uint32_t a;
    asm("{ .reg .u64 t; cvta.to.shared.u64 t, %1; cvt.u32.u64 %0, t; }" : "=r"(a) : "l"(p));
    return a;
}
__device__ __forceinline__ void cp_async16(uint32_t s, const void* g) {
    asm volatile("cp.async.cg.shared.global [%0], [%1], 16;" :: "r"(s), "l"(g));
}
__device__ __forceinline__ void cp_commit() { asm volatile("cp.async.commit_group;"); }

__device__ __forceinline__ void mma_f32f16(float* d, const uint32_t* a, uint32_t b0, uint32_t b1) {
    asm volatile(
        "mma.sync.aligned.m16n8k16.row.col.f32.f16.f16.f32 "
        "{%0,%1,%2,%3}, {%4,%5,%6,%7}, {%8,%9}, {%0,%1,%2,%3};"
        : "+f"(d[0]), "+f"(d[1]), "+f"(d[2]), "+f"(d[3])
        : "r"(a[0]), "r"(a[1]), "r"(a[2]), "r"(a[3]), "r"(b0), "r"(b1));
}
__device__ __forceinline__ void mma_f16acc(uint32_t* d, const uint32_t* a, uint32_t b0, uint32_t b1) {
    asm volatile(
        "mma.sync.aligned.m16n8k16.row.col.f16.f16.f16.f16 "
        "{%0,%1}, {%2,%3,%4,%5}, {%6,%7}, {%0,%1};"
        : "+r"(d[0]), "+r"(d[1])
        : "r"(a[0]), "r"(a[1]), "r"(a[2]), "r"(a[3]), "r"(b0), "r"(b1));
}
__device__ __forceinline__ uint32_t h2ex2(uint32_t x) {
    uint32_t y; asm("ex2.approx.f16x2 %0, %1;" : "=r"(y) : "r"(x)); return y;
}
__device__ __forceinline__ void ldsm4(uint32_t* r, uint32_t addr) {
    asm volatile("ldmatrix.sync.aligned.m8n8.x4.shared.b16 {%0,%1,%2,%3}, [%4];"
        : "=r"(r[0]), "=r"(r[1]), "=r"(r[2]), "=r"(r[3]) : "r"(addr));
}
__device__ __forceinline__ void ldsm4t(uint32_t* r, uint32_t addr) {
    asm volatile("ldmatrix.sync.aligned.m8n8.x4.trans.shared.b16 {%0,%1,%2,%3}, [%4];"
        : "=r"(r[0]), "=r"(r[1]), "=r"(r[2]), "=r"(r[3]) : "r"(addr));
}
__device__ __forceinline__ uint32_t packhf(float a, float b) {
    __half2 t = __floats2half2_rn(a, b);
    return *reinterpret_cast<uint32_t*>(&t);
}

// ---------- kernel 1: BN partial sums ----------
__global__ __launch_bounds__(256) void bn_part(const float* __restrict__ x) {
    int c = blockIdx.x >> 3, s = blockIdx.x & 7, t = threadIdx.x;
    const float* p = x + ((size_t)s * C + c) * HW;
    float sm = 0.f, sq = 0.f;
#pragma unroll
    for (int i = 0; i < HW / 256; i++) { float v = p[t + i * 256]; sm += v; sq += v * v; }
    __shared__ float rs[256], rq[256];
    rs[t] = sm; rq[t] = sq; __syncthreads();
    for (int o = 128; o > 0; o >>= 1) {
        if (t < o) { rs[t] += rs[t + o]; rq[t] += rq[t + o]; }
        __syncthreads();
    }
    if (t == 0) { g_ps[c * 8 + s] = rs[0]; g_pq[c * 8 + s] = rq[0]; }
}

// ---------- kernel 2: BN-finalize + BN-apply + QKV via HMMA (fp16) ----------
__global__ __launch_bounds__(128) void qkv_kernel(
    const float* __restrict__ x,
    const float* __restrict__ gamma, const float* __restrict__ beta,
    const float* __restrict__ wq, const float* __restrict__ bq,
    const float* __restrict__ wk, const float* __restrict__ bk,
    const float* __restrict__ wv, const float* __restrict__ bv) {
    __shared__ __align__(16) char sX[128 * 128];
    __shared__ __align__(16) char sW[3][64 * 128];
    __shared__ float ssc[C], ssh[C];
    int t = threadIdx.x, wid = t >> 5, l = t & 31;
    int n = blockIdx.y;
    int p0 = blockIdx.x * 128;
    uint32_t sXa = smem_u32(sX);

    // per-CTA BN finalize (redundant, tiny)
    if (t < C) {
        float sm = 0.f, sq = 0.f;
#pragma unroll
        for (int k = 0; k < 8; k++) { sm += g_ps[t * 8 + k]; sq += g_pq[t * 8 + k]; }
        float inv = 1.0f / (float)(NB * HW);
        float mean = sm * inv;
        float var = sq * inv - mean * mean;
        float sc = rsqrtf(var + EPS_BN) * gamma[t];
        ssc[t] = sc;
        ssh[t] = beta[t] - mean * sc;
    }
    __syncthreads();

    {
        const float* xb = x + (size_t)n * C * HW + p0 + t;
        int r7 = t & 7;
#pragma unroll
        for (int cp = 0; cp < 32; cp++) {
            int c0 = 2 * cp;
            float v0 = xb[(size_t)c0 * HW] * ssc[c0] + ssh[c0];
            float v1 = xb[(size_t)(c0 + 1) * HW] * ssc[c0 + 1] + ssh[c0 + 1];
            uint32_t pk = packhf(v0, v1);
            uint32_t off = ((uint32_t)(((c0 >> 3) ^ r7) << 4)) + (uint32_t)((c0 & 7) * 2);
            *reinterpret_cast<uint32_t*>(&((char*)sX)[t * 128 + off]) = pk;
        }
    }
    {
        const float* ws[3] = {wq, wk, wv};
#pragma unroll
        for (int w = 0; w < 3; w++) {
            const float* wp = ws[w];
#pragma unroll
            for (int i = 0; i < 16; i++) {
                int idx = t + i * 128;
                int o = idx >> 5, cp = idx & 31, c0 = 2 * cp;
                float2 wv2 = *reinterpret_cast<const float2*>(wp + o * 64 + c0);
                uint32_t pk = packhf(wv2.x, wv2.y);
                uint32_t off = ((uint32_t)(((c0 >> 3) ^ (o & 7)) << 4)) + (uint32_t)((c0 & 7) * 2);
                *reinterpret_cast<uint32_t*>(&sW[w][o * 128 + off]) = pk;
            }
        }
    }
    __syncthreads();

    uint32_t A[2][4][4];
    {
        int arow = (l & 7) + ((l >> 3) & 1) * 8;
        int l7 = l & 7;
#pragma unroll
        for (int mt2 = 0; mt2 < 2; mt2++) {
            int m0 = (wid * 2 + mt2) * 16;
#pragma unroll
            for (int kt = 0; kt < 4; kt++) {
                uint32_t chunk = (uint32_t)((kt * 2 + (l >> 4)) ^ l7);
                ldsm4(A[mt2][kt], sXa + (uint32_t)(m0 + arow) * 128 + (chunk << 4));
            }
        }
    }

    const float* biases[3] = {bq, bk, bv};
    __half* outs[3] = {g_Q + (size_t)n * HW * C + (size_t)p0 * C,
                       g_Kb + (size_t)n * HW * C + (size_t)p0 * C,
                       g_V + (size_t)n * HW * C + (size_t)p0 * C};
    float scales[3] = {QSCALE, 1.f, 1.f};

    int brow = l & 7;
    uint32_t bx0 = (uint32_t)(((0 + (l >> 3)) ^ brow) << 4);
    uint32_t bx4 = (uint32_t)(((4 + (l >> 3)) ^ brow) << 4);

#pragma unroll
    for (int w = 0; w < 3; w++) {
        uint32_t sWa = smem_u32(sW[w]);
        float acc[2][8][4];
#pragma unroll
        for (int a = 0; a < 2; a++)
#pragma unroll
            for (int b = 0; b < 8; b++)
#pragma unroll
                for (int cc = 0; cc < 4; cc++) acc[a][b][cc] = 0.f;

#pragma unroll
        for (int nt = 0; nt < 8; nt++) {
            uint32_t base = sWa + (uint32_t)(nt * 8 + brow) * 128;
            uint32_t B[8];
            ldsm4(B, base + bx0);
            ldsm4(B + 4, base + bx4);
#pragma unroll
            for (int mt2 = 0; mt2 < 2; mt2++) {
                mma_f32f16(acc[mt2][nt], A[mt2][0], B[0], B[1]);
                mma_f32f16(acc[mt2][nt], A[mt2][1], B[2], B[3]);
                mma_f32f16(acc[mt2][nt], A[mt2][2], B[4], B[5]);
                mma_f32f16(acc[mt2][nt], A[mt2][3], B[6], B[7]);
            }
        }
        const float* bias = biases[w];
        float s = scales[w];
        __half* op = outs[w];
#pragma unroll
        for (int nt = 0; nt < 8; nt++) {
            int col = nt * 8 + (l & 3) * 2;
            float2 bb = *reinterpret_cast<const float2*>(bias + col);
#pragma unroll
            for (int mt2 = 0; mt2 < 2; mt2++) {
                int row0 = (wid * 2 + mt2) * 16 + (l >> 2);
                uint32_t pk0 = packhf((acc[mt2][nt][0] + bb.x) * s, (acc[mt2][nt][1] + bb.y) * s);
                uint32_t pk1 = packhf((acc[mt2][nt][2] + bb.x) * s, (acc[mt2][nt][3] + bb.y) * s);
                *reinterpret_cast<uint32_t*>(op + (size_t)row0 * C + col) = pk0;
                *reinterpret_cast<uint32_t*>(op + (size_t)(row0 + 8) * C + col) = pk1;
            }
        }
    }
}

// ---------- kernel 3: flash attention (fp16, fully flattened MMA1) ----------
constexpr int ROWB = 144;

__global__ __launch_bounds__(128) void attn_kernel() {
    __shared__ __align__(16) char sK[2][KT * ROWB];
    __shared__ __align__(16) char sV[2][KT * ROWB];
    int t = threadIdx.x, wid = t >> 5, lane = t & 31;
    int n = blockIdx.y, qt = blockIdx.x;
    int qrow0 = qt * QT + wid * 32;
    int m = lane >> 2;
    int qp = (lane & 3) * 2;

    const __half* Kg = g_Kb + (size_t)n * HW * C;
    const __half* Vg = g_V + (size_t)n * HW * C;

    uint32_t lds_off = (uint32_t)((lane & 7) * ROWB + (lane >> 3) * 16);
    uint32_t ldt_off = (uint32_t)(((lane & 7) + ((lane >> 3) & 1) * 8) * ROWB + (lane >> 4) * 16);
    uint32_t sKa = smem_u32(sK);
    uint32_t sVa = smem_u32(sV);

    uint32_t qa[2][4][4];
#pragma unroll
    for (int mt = 0; mt < 2; mt++) {
        const __half* Qb = g_Q + ((size_t)n * HW + qrow0 + mt * 16) * C;
#pragma unroll
        for (int kb = 0; kb < 4; kb++) {
            qa[mt][kb][0] = *(const uint32_t*)(Qb + (size_t)m * C + kb * 16 + qp);
            qa[mt][kb][1] = *(const uint32_t*)(Qb + (size_t)(m + 8) * C + kb * 16 + qp);
            qa[mt][kb][2] = *(const uint32_t*)(Qb + (size_t)m * C + kb * 16 + 8 + qp);
            qa[mt][kb][3] = *(const uint32_t*)(Qb + (size_t)(m + 8) * C + kb * 16 + 8 + qp);
        }
    }

    float oacc[2][8][4];
#pragma unroll
    for (int mt = 0; mt < 2; mt++)
#pragma unroll
        for (int i = 0; i < 8; i++)
#pragma unroll
            for (int j = 0; j < 4; j++) oacc[mt][i][j] = 0.f;
    float lacc[2][4];
#pragma unroll
    for (int mt = 0; mt < 2; mt++)
#pragma unroll
        for (int j = 0; j < 4; j++) lacc[mt][j] = 0.f;

    auto prefetch = [&](int b, int kt) {
#pragma unroll
        for (int rr = 0; rr < 4; rr++) {
            int ch = t + rr * 128;
            int row = ch >> 3, col = ch & 7;
            cp_async16(sKa + (uint32_t)(b * KT * ROWB + row * ROWB + col * 16),
                       Kg + ((size_t)(kt * KT + row)) * C + col * 8);
            cp_async16(sVa + (uint32_t)(b * KT * ROWB + row * ROWB + col * 16),
                       Vg + ((size_t)(kt * KT + row)) * C + col * 8);
        }
        cp_commit();
    };

    prefetch(0, 0);

    for (int kt = 0; kt < NKT; kt++) {
        asm volatile("cp.async.wait_group 0;");
        __syncthreads();
        if (kt + 1 < NKT) prefetch((kt + 1) & 1, kt + 1);

        uint32_t kb_a = sKa + (uint32_t)((kt & 1) * KT * ROWB) + lds_off;
        uint32_t vb_a = sVa + (uint32_t)((kt & 1) * KT * ROWB) + ldt_off;

        // ---- MMA1: all 64 S-MMAs, 16 independent fp16-accum chains ----
        uint32_t s16[2][8][2];
#pragma unroll
        for (int nt = 0; nt < 8; nt++) {
            uint32_t B[8];
            ldsm4(B, kb_a + nt * 8 * ROWB);
            ldsm4(B + 4, kb_a + nt * 8 * ROWB + 64);
            s16[0][nt][0] = 0u; s16[0][nt][1] = 0u;
            s16[1][nt][0] = 0u; s16[1][nt][1] = 0u;
#pragma unroll
            for (int kb = 0; kb < 4; kb++) {
                mma_f16acc(s16[0][nt], qa[0][kb], B[2 * kb], B[2 * kb + 1]);
                mma_f16acc(s16[1][nt], qa[1][kb], B[2 * kb], B[2 * kb + 1]);
            }
        }

        // ---- softmax: 32 packed ex2, then 8 rowsum MMAs ----
        uint32_t pa[2][4][4];
#pragma unroll
        for (int kc = 0; kc < 4; kc++) {
#pragma unroll
            for (int mt = 0; mt < 2; mt++) {
                pa[mt][kc][0] = h2ex2(s16[mt][2 * kc][0]);
                pa[mt][kc][1] = h2ex2(s16[mt][2 * kc][1]);
                pa[mt][kc][2] = h2ex2(s16[mt][2 * kc + 1][0]);
                pa[mt][kc][3] = h2ex2(s16[mt][2 * kc + 1][1]);
            }
        }
#pragma unroll
        for (int kc = 0; kc < 4; kc++) {
            mma_f32f16(lacc[0], pa[0][kc], ONE2, ONE2);
            mma_f32f16(lacc[1], pa[1][kc], ONE2, ONE2);
        }

        // ---- MMA2: kc-outer, 16 independent accumulators per kc ----
#pragma unroll
        for (int kc = 0; kc < 4; kc++) {
            uint32_t B[16];
#pragma unroll
            for (int np = 0; np < 4; np++)
                ldsm4t(B + 4 * np, vb_a + (uint32_t)(kc * 16 * ROWB + np * 32));
#pragma unroll
            for (int np = 0; np < 4; np++) {
#pragma unroll
                for (int mt = 0; mt < 2; mt++) {
                    mma_f32f16(oacc[mt][2 * np],     pa[mt][kc], B[4 * np],     B[4 * np + 1]);
                    mma_f32f16(oacc[mt][2 * np + 1], pa[mt][kc], B[4 * np + 2], B[4 * np + 3]);
                }
            }
        }
    }

#pragma unroll
    for (int mt = 0; mt < 2; mt++) {
        float inv0 = 1.f / lacc[mt][0];
        float inv1 = 1.f / lacc[mt][2];

        float* orow0 = g_O + ((size_t)n * HW + qrow0 + mt * 16 + m) * C;
        float* orow1 = orow0 + 8 * C;
#pragma unroll
        for (int ct = 0; ct < 8; ct++) {
            int col = ct * 8 + qp;
            float2 v0 = make_float2(oacc[mt][ct][0] * inv0, oacc[mt][ct][1] * inv0);
            float2 v1 = make_float2(oacc[mt][ct][2] * inv1, oacc[mt][ct][3] * inv1);
            *reinterpret_cast<float2*>(orow0 + col) = v0;
            *reinterpret_cast<float2*>(orow1 + col) = v1;
        }
    }
}

// ---------- kernel 4: output conv via HMMA (fp16) + residual ----------
__global__ __launch_bounds__(128) void out_kernel(
    const float* __restrict__ x, const float* __restrict__ wo,
    const float* __restrict__ bo, float* __restrict__ out) {
    __shared__ __align__(16) char smem[24576];
    int t = threadIdx.x, wid = t >> 5, l = t & 31;
    int n = blockIdx.y;
    int p0 = blockIdx.x * 128;
    uint32_t sOa = smem_u32(smem);
    uint32_t sWa = sOa + 16384;

    {
        const float* Ob = g_O + (size_t)n * C * HW + p0 + t;
        int r7 = t & 7;
#pragma unroll
        for (int cp = 0; cp < 32; cp++) {
            int c0 = 2 * cp;
            float v0 = Ob[(size_t)c0 * HW];
            float v1 = Ob[(size_t)(c0 + 1) * HW];
            uint32_t pk = packhf(v0, v1);
            uint32_t off = ((uint32_t)(((c0 >> 3) ^ r7) << 4)) + (uint32_t)((c0 & 7) * 2);
            *reinterpret_cast<uint32_t*>(&smem[t * 128 + off]) = pk;
        }
    }
#pragma unroll
    for (int i = 0; i < 16; i++) {
        int idx = t + i * 128;
        int o = idx >> 5, cp = idx & 31, c0 = 2 * cp;
        float2 wv2 = *reinterpret_cast<const float2*>(wo + o * 64 + c0);
        uint32_t pk = packhf(wv2.x, wv2.y);
        uint32_t off = ((uint32_t)(((c0 >> 3) ^ (o & 7)) << 4)) + (uint32_t)((c0 & 7) * 2);
        *reinterpret_cast<uint32_t*>(&smem[16384 + o * 128 + off]) = pk;
    }
    __syncthreads();

    uint32_t A[2][4][4];
    {
        int arow = (l & 7) + ((l >> 3) & 1) * 8;
        int l7 = l & 7;
#pragma unroll
        for (int mt2 = 0; mt2 < 2; mt2++) {
            int m0 = (wid * 2 + mt2) * 16;
#pragma unroll
            for (int kt = 0; kt < 4; kt++) {
                uint32_t chunk = (uint32_t)((kt * 2 + (l >> 4)) ^ l7);
                ldsm4(A[mt2][kt], sOa + (uint32_t)(m0 + arow) * 128 + (chunk << 4));
            }
        }
    }

    int brow = l & 7;
    uint32_t bx0 = (uint32_t)(((0 + (l >> 3)) ^ brow) << 4);
    uint32_t bx4 = (uint32_t)(((4 + (l >> 3)) ^ brow) << 4);

    float acc[2][8][4];
#pragma unroll
    for (int a = 0; a < 2; a++)
#pragma unroll
        for (int b = 0; b < 8; b++)
#pragma unroll
            for (int cc = 0; cc < 4; cc++) acc[a][b][cc] = 0.f;

#pragma unroll
    for (int nt = 0; nt < 8; nt++) {
        uint32_t base = sWa + (uint32_t)(nt * 8 + brow) * 128;
        uint32_t B[8];
        ldsm4(B, base + bx0);
        ldsm4(B + 4, base + bx4);
#pragma unroll
        for (int mt2 = 0; mt2 < 2; mt2++) {
            mma_f32f16(acc[mt2][nt], A[mt2][0], B[0], B[1]);
            mma_f32f16(acc[mt2][nt], A[mt2][1], B[2], B[3]);
            mma_f32f16(acc[mt2][nt], A[mt2][2], B[4], B[5]);
            mma_f32f16(acc[mt2][nt], A[mt2][3], B[6], B[7]);
        }
    }
    __syncthreads();

#pragma unroll
    for (int nt = 0; nt < 8; nt++) {
        int col = nt * 8 + (l & 3) * 2;
        float2 bb = *reinterpret_cast<const float2*>(bo + col);
#pragma unroll
        for (int mt2 = 0; mt2 < 2; mt2++) {
            int row0 = (wid * 2 + mt2) * 16 + (l >> 2);
            *reinterpret_cast<__half*>(&smem[col * 264 + row0 * 2])       = __float2half(acc[mt2][nt][0] + bb.x);
            *reinterpret_cast<__half*>(&smem[(col + 1) * 264 + row0 * 2]) = __float2half(acc[mt2][nt][1] + bb.y);
            *reinterpret_cast<__half*>(&smem[col * 264 + (row0 + 8) * 2])       = __float2half(acc[mt2][nt][2] + bb.x);
            *reinterpret_cast<__half*>(&smem[(col + 1) * 264 + (row0 + 8) * 2]) = __float2half(acc[mt2][nt][3] + bb.y);
        }
    }
    __syncthreads();

#pragma unroll
    for (int oo = 0; oo < 16; oo++) {
        int o = wid * 16 + oo;
        uint2 pk = *reinterpret_cast<const uint2*>(&smem[o * 264 + l * 8]);
        __half2 b01 = *reinterpret_cast<__half2*>(&pk.x);
        __half2 b23 = *reinterpret_cast<__half2*>(&pk.y);
        const float* xb = x + ((size_t)n * C + o) * HW + p0 + l * 4;
        float4 xv = *reinterpret_cast<const float4*>(xb);
        float4 r;
        r.x = __half2float(b01.x) + xv.x;
        r.y = __half2float(b01.y) + xv.y;
        r.z = __half2float(b23.x) + xv.z;
        r.w = __half2float(b23.y) + xv.w;
        *reinterpret_cast<float4*>(out + ((size_t)n * C + o) * HW + p0 + l * 4) = r;
    }
}

extern "C" void kernel_launch(void* const* d_in, const int* in_sizes, int n_in,
                              void* d_out, int out_size) {
    const float* x     = (const float*)d_in[0];
    const float* gamma = (const float*)d_in[1];
    const float* beta  = (const float*)d_in[2];
    const float* wq    = (const float*)d_in[3];
    const float* bq    = (const float*)d_in[4];
    const float* wk    = (const float*)d_in[5];
    const float* bk    = (const float*)d_in[6];
    const float* wv    = (const float*)d_in[7];
    const float* bv    = (const float*)d_in[8];
    const float* wo    = (const float*)d_in[9];
    const float* bo    = (const float*)d_in[10];
    float* out = (float*)d_out;

    bn_part<<<512, 256>>>(x);
    qkv_kernel<<<dim3(HW / 128, NB), 128>>>(x, gamma, beta, wq, bq, wk, bk, wv, bv);
    attn_kernel<<<dim3(HW / QT, NB), 128>>>();
    out_kernel<<<dim3(HW / 128, NB), 128>>>(x, wo, bo, out);
}